// round 1
// baseline (speedup 1.0000x reference)
#include <cuda_runtime.h>

// Mip pyramid scratch for levels 1..7 (level 0 = fm read in place).
// Texel counts per plane: 256^2+128^2+64^2+32^2+16^2+8^2+4^2 = 87376 texels,
// 16 channels = 4 float4 each. 3 planes.
#define PYR_PLANE_TEXELS 87376
#define PYR_PLANE_F4     (PYR_PLANE_TEXELS * 4)
__device__ float4 g_pyr[3 * PYR_PLANE_F4];   // ~16.8 MB static scratch

// Texel offset of level l (1..7) within a plane's scratch region.
__constant__ int c_off[8] = {0, 0, 65536, 81920, 86016, 87040, 87296, 87360};

// ---------------------------------------------------------------------------
// Downsample level (l-1) -> l with a 2x2 box filter.
// One thread per (plane, y, x, c4). c4 fastest => coalesced 64B reads/writes.
// ---------------------------------------------------------------------------
__global__ void downsample_kernel(const float4* __restrict__ fm, int l) {
    const int s     = 512 >> l;       // output size
    const int shift = 9 - l;          // log2(s)
    const int total = 3 * s * s * 4;
    int idx = blockIdx.x * blockDim.x + threadIdx.x;
    if (idx >= total) return;

    const int c4 = idx & 3;
    int t = idx >> 2;
    const int x     = t & (s - 1);
    const int y     = (t >> shift) & (s - 1);
    const int plane = t >> (2 * shift);

    const int S = s << 1;             // input size

    const float4* src;
    if (l == 1) {
        src = fm + plane * (512 * 512 * 4);
    } else {
        src = g_pyr + plane * PYR_PLANE_F4 + c_off[l - 1] * 4;
    }
    float4* dst = g_pyr + plane * PYR_PLANE_F4 + c_off[l] * 4;

    const int xi = x << 1, yi = y << 1;
    const float4 a = __ldg(src + (yi * S + xi) * 4 + c4);
    const float4 b = __ldg(src + (yi * S + xi + 1) * 4 + c4);
    const float4 c = __ldg(src + ((yi + 1) * S + xi) * 4 + c4);
    const float4 d = __ldg(src + ((yi + 1) * S + xi + 1) * 4 + c4);

    float4 r;
    r.x = (a.x + b.x + c.x + d.x) * 0.25f;
    r.y = (a.y + b.y + c.y + d.y) * 0.25f;
    r.z = (a.z + b.z + c.z + d.z) * 0.25f;
    r.w = (a.w + b.w + c.w + d.w) * 0.25f;
    dst[(y * s + x) * 4 + c4] = r;
}

// ---------------------------------------------------------------------------
// Bilinear fetch of one float4 (channel quad c4) at mip level li.
// ---------------------------------------------------------------------------
__device__ __forceinline__ float4 bilin(const float4* __restrict__ fm,
                                        int plane, int li,
                                        float u, float v, int c4) {
    const int size = 512 >> li;
    const float4* base;
    if (li == 0) {
        base = fm + plane * (512 * 512 * 4);
    } else {
        base = g_pyr + plane * PYR_PLANE_F4 + c_off[li] * 4;
    }
    const float fs = (float)size;
    const float px = u * fs - 0.5f;
    const float py = v * fs - 0.5f;
    const float x0f = floorf(px);
    const float y0f = floorf(py);
    const float fx = px - x0f;
    const float fy = py - y0f;
    const int x0 = (int)x0f;
    const int y0 = (int)y0f;
    const int sm1 = size - 1;
    const int xa = min(max(x0, 0), sm1);
    const int xb = min(max(x0 + 1, 0), sm1);
    const int ya = min(max(y0, 0), sm1);
    const int yb = min(max(y0 + 1, 0), sm1);

    const float4 f00 = __ldg(base + (ya * size + xa) * 4 + c4);
    const float4 f01 = __ldg(base + (ya * size + xb) * 4 + c4);
    const float4 f10 = __ldg(base + (yb * size + xa) * 4 + c4);
    const float4 f11 = __ldg(base + (yb * size + xb) * 4 + c4);

    const float w00 = (1.f - fx) * (1.f - fy);
    const float w01 = fx * (1.f - fy);
    const float w10 = (1.f - fx) * fy;
    const float w11 = fx * fy;

    float4 r;
    r.x = f00.x * w00 + f01.x * w01 + f10.x * w10 + f11.x * w11;
    r.y = f00.y * w00 + f01.y * w01 + f10.y * w10 + f11.y * w11;
    r.z = f00.z * w00 + f01.z * w01 + f10.z * w10 + f11.z * w11;
    r.w = f00.w * w00 + f01.w * w01 + f10.w * w10 + f11.w * w11;
    return r;
}

// ---------------------------------------------------------------------------
// Sampling kernel: one thread per (point, plane, channel-quad).
// idx layout: c4 fastest (coalesced texel reads + output writes), then plane,
// then point.
// ---------------------------------------------------------------------------
__global__ void sample_kernel(const float* __restrict__ xin,
                              const float* __restrict__ level,
                              const float4* __restrict__ fm,
                              float4* __restrict__ out, int N) {
    int idx = blockIdx.x * blockDim.x + threadIdx.x;
    if (idx >= N * 12) return;

    const int c4 = idx & 3;
    int t = idx >> 2;
    const int plane = t % 3;
    const int pt = t / 3;

    const float xv = __ldg(xin + pt * 3 + 0);
    const float yv = __ldg(xin + pt * 3 + 1);
    const float zv = __ldg(xin + pt * 3 + 2);

    float u, v;
    if (plane == 0)      { u = yv; v = zv; }
    else if (plane == 1) { u = xv; v = zv; }
    else                 { u = xv; v = yv; }

    float lvl = __ldg(level + pt);
    lvl = fminf(fmaxf(lvl, 0.f), 7.f);
    const float l0f = floorf(lvl);
    const float f = lvl - l0f;
    const int l0 = (int)l0f;
    const int l1 = min(l0 + 1, 7);

    const float4 s0 = bilin(fm, plane, l0, u, v, c4);
    const float4 s1 = bilin(fm, plane, l1, u, v, c4);

    float4 r;
    r.x = s0.x + f * (s1.x - s0.x);
    r.y = s0.y + f * (s1.y - s0.y);
    r.z = s0.z + f * (s1.z - s0.z);
    r.w = s0.w + f * (s1.w - s0.w);

    out[pt * 12 + plane * 4 + c4] = r;
}

extern "C" void kernel_launch(void* const* d_in, const int* in_sizes, int n_in,
                              void* d_out, int out_size) {
    const float*  x     = (const float*)d_in[0];
    const float*  level = (const float*)d_in[1];
    const float4* fm    = (const float4*)d_in[2];
    float4* out = (float4*)d_out;
    const int N = in_sizes[0] / 3;

    // Build mip pyramid levels 1..7
    for (int l = 1; l <= 7; ++l) {
        const int s = 512 >> l;
        const int total = 3 * s * s * 4;
        const int threads = 256;
        const int blocks = (total + threads - 1) / threads;
        downsample_kernel<<<blocks, threads>>>(fm, l);
    }

    // Sample
    const int total = N * 12;
    const int threads = 256;
    const int blocks = (total + threads - 1) / threads;
    sample_kernel<<<blocks, threads>>>(x, level, fm, out, N);
}